// round 5
// baseline (speedup 1.0000x reference)
#include <cuda_runtime.h>
#include <cstdint>

#define Hh 56
#define Ww 56
#define HO 58
#define WO 58
#define PLANE_IN  3136   // 56*56
#define PLANE_OUT 3364   // 58*58
// C is fixed at 128 by the generator
#define C_LOG2 7
#define C_MASK 127

__global__ void __launch_bounds__(256, 7)
weight_pad2d_kernel(const float* __restrict__ x,
                    const float* __restrict__ topW,
                    const float* __restrict__ botW,
                    const float* __restrict__ leftW,
                    const float* __restrict__ rightW,
                    const float* __restrict__ topleftW,
                    const float* __restrict__ toprightW,
                    const float* __restrict__ botleftW,
                    const float* __restrict__ botrightW,
                    const int* __restrict__ num_patches_ptr,
                    int planes,
                    float* __restrict__ out)
{
    const int tid  = threadIdx.x;
    const int warp = tid >> 5;           // 0..7 -> one warp per row-group
    const int lane = tid & 31;

    const int P  = *num_patches_ptr;
    const int PP = P * P;

    const bool ld = (lane < 28);         // lanes 0..27 carry data

    for (int plane = blockIdx.x; plane < planes; plane += gridDim.x) {
        const int bidx = plane >> C_LOG2;
        const int ch   = plane & C_MASK;

        const unsigned q1 = (unsigned)bidx / (unsigned)P;
        const int colp    = bidx - (int)(q1 * (unsigned)P);       // bidx % P
        const unsigned q2 = (unsigned)bidx / (unsigned)PP;
        const int within  = bidx - (int)(q2 * (unsigned)PP);      // bidx % PP

        const bool topz   = within < P;
        const bool botz   = within >= PP - P;
        const bool leftz  = colp == 0;
        const bool rightz = colp == P - 1;

        const float* __restrict__ xp = x   + (size_t)plane * PLANE_IN;
        float*       __restrict__ op = out + (size_t)plane * PLANE_OUT;

        const float wLr = leftz  ? 0.0f : leftW[ch];
        const float wRr = rightz ? 0.0f : rightW[ch];

        // ---- phase 1: batch all loads (MLP = 7-8) ----
        float2 g[7];
        #pragma unroll
        for (int k = 0; k < 7; k++) {
            g[k] = make_float2(0.0f, 0.0f);
            if (ld) g[k] = *(const float2*)(xp + (warp + 8 * k) * Ww + 2 * lane);
        }
        // extra row for the peeled edge rows: row1 for warp0, row54 for warp7
        float2 gx = make_float2(0.0f, 0.0f);
        if ((warp == 0 || warp == 7) && ld) {
            const int ir = (warp == 0) ? 1 : (Hh - 2);
            gx = *(const float2*)(xp + ir * Ww + 2 * lane);
        }

        // ---- phase 2: interior rows r = 1..56 (warp w: rows 1+w, 9+w, ...) ----
        #pragma unroll
        for (int k = 0; k < 7; k++) {
            const int r = 1 + warp + 8 * k;
            const float upy = __shfl_up_sync(0xffffffffu, g[k].y, 1);
            if (ld) {
                const float o_lo = (lane == 0) ? wLr * (g[k].x + g[k].y) : upy;
                const float o_hi = g[k].x;
                *(float2*)(op + r * WO + 2 * lane) = make_float2(o_lo, o_hi);
                if (lane == 27) {
                    *(float2*)(op + r * WO + 56) =
                        make_float2(g[k].y, wRr * (g[k].x + g[k].y));
                }
            }
        }

        // ---- top row r=0 (warp 0; g[0]=row0, gx=row1) ----
        if (warp == 0) {
            const float wT = topz ? 0.0f : topW[ch];
            const float tl = (topz || leftz)  ? 0.0f : topleftW[ch];
            const float tr = (topz || rightz) ? 0.0f : toprightW[ch];
            const float2 h = make_float2(g[0].x + gx.x, g[0].y + gx.y);
            const float hy_up = __shfl_up_sync(0xffffffffu, h.y, 1);
            if (ld) {
                const float o_lo = (lane == 0) ? tl * g[0].x : wT * hy_up;
                const float o_hi = wT * h.x;
                *(float2*)(op + 2 * lane) = make_float2(o_lo, o_hi);
                if (lane == 27) {
                    *(float2*)(op + 56) = make_float2(wT * h.y, tr * g[0].y);
                }
            }
        }

        // ---- bottom row r=57 (warp 7; g[6]=row55, gx=row54) ----
        if (warp == 7) {
            const float wB = botz ? 0.0f : botW[ch];
            const float bl = (botz || leftz)  ? 0.0f : botleftW[ch];
            const float br = (botz || rightz) ? 0.0f : botrightW[ch];
            const float2 h = make_float2(g[6].x + gx.x, g[6].y + gx.y);
            const float hy_up = __shfl_up_sync(0xffffffffu, h.y, 1);
            float* __restrict__ orow = op + (HO - 1) * WO;
            if (ld) {
                const float o_lo = (lane == 0) ? bl * g[6].x : wB * hy_up;
                const float o_hi = wB * h.x;
                *(float2*)(orow + 2 * lane) = make_float2(o_lo, o_hi);
                if (lane == 27) {
                    *(float2*)(orow + 56) = make_float2(wB * h.y, br * g[6].y);
                }
            }
        }
    }
}

extern "C" void kernel_launch(void* const* d_in, const int* in_sizes, int n_in,
                              void* d_out, int out_size)
{
    const float* x         = (const float*)d_in[0];
    const float* topW      = (const float*)d_in[1];
    const float* botW      = (const float*)d_in[2];
    const float* leftW     = (const float*)d_in[3];
    const float* rightW    = (const float*)d_in[4];
    const float* topleftW  = (const float*)d_in[5];
    const float* toprightW = (const float*)d_in[6];
    const float* botleftW  = (const float*)d_in[7];
    const float* botrightW = (const float*)d_in[8];
    const int*   num_patches = (const int*)d_in[10];

    const int planes = in_sizes[0] / PLANE_IN;   // b * C = 16384

    int grid = 148 * 8;
    if (grid > planes) grid = planes;

    weight_pad2d_kernel<<<grid, 256>>>(
        x, topW, botW, leftW, rightW,
        topleftW, toprightW, botleftW, botrightW,
        num_patches, planes, (float*)d_out);
}

// round 6
// speedup vs baseline: 1.0959x; 1.0959x over previous
#include <cuda_runtime.h>
#include <cstdint>

#define Hh 56
#define Ww 56
#define HO 58
#define WO 58
#define PLANE_IN  3136   // 56*56
#define PLANE_OUT 3364   // 58*58
// C fixed at 128 by the generator
#define C_LOG2 7
#define C_MASK 127

__global__ void __launch_bounds__(256, 8)
weight_pad2d_kernel(const float* __restrict__ x,
                    const float* __restrict__ topW,
                    const float* __restrict__ botW,
                    const float* __restrict__ leftW,
                    const float* __restrict__ rightW,
                    const float* __restrict__ topleftW,
                    const float* __restrict__ toprightW,
                    const float* __restrict__ botleftW,
                    const float* __restrict__ botrightW,
                    const int* __restrict__ num_patches_ptr,
                    int planes,
                    float* __restrict__ out)
{
    const int tid  = threadIdx.x;
    const int warp = tid >> 5;           // 0..7
    const int lane = tid & 31;

    const int P  = *num_patches_ptr;
    const int PP = P * P;

    const bool ld = (lane < 28);   // lanes 0..27 load (56 floats)
    const bool st = (lane < 29);   // lanes 0..28 store (58 floats)

    for (int plane = blockIdx.x; plane < planes; plane += gridDim.x) {
        const int bidx = plane >> C_LOG2;
        const int ch   = plane & C_MASK;

        const unsigned q1 = (unsigned)bidx / (unsigned)P;
        const int colp    = bidx - (int)(q1 * (unsigned)P);       // bidx % P
        const unsigned q2 = (unsigned)bidx / (unsigned)PP;
        const int within  = bidx - (int)(q2 * (unsigned)PP);      // bidx % PP

        const bool topz   = within < P;
        const bool botz   = within >= PP - P;
        const bool leftz  = colp == 0;
        const bool rightz = colp == (P - 1);

        const float* __restrict__ xp = x   + (size_t)plane * PLANE_IN;
        float*       __restrict__ op = out + (size_t)plane * PLANE_OUT;

        // ---- peeled top row (r=0): warps 0,1 scalar ----
        if (tid < 64) {
            const int c = tid;
            if (c < WO) {
                float v;
                if (c == 0) {
                    v = (topz || leftz) ? 0.0f : topleftW[ch] * __ldcs(xp);
                } else if (c == WO - 1) {
                    v = (topz || rightz) ? 0.0f : toprightW[ch] * __ldcs(xp + Ww - 1);
                } else {
                    v = topz ? 0.0f : topW[ch] * (__ldcs(xp + c - 1) + __ldcs(xp + Ww + c - 1));
                }
                __stcs(op + c, v);
            }
        } else if (tid < 128) {
            // ---- peeled bottom row (r=57): warps 2,3 scalar ----
            const int c = tid - 64;
            if (c < WO) {
                const float* x54 = xp + (Hh - 2) * Ww;
                const float* x55 = xp + (Hh - 1) * Ww;
                float v;
                if (c == 0) {
                    v = (botz || leftz) ? 0.0f : botleftW[ch] * __ldcs(x55);
                } else if (c == WO - 1) {
                    v = (botz || rightz) ? 0.0f : botrightW[ch] * __ldcs(x55 + Ww - 1);
                } else {
                    v = botz ? 0.0f : botW[ch] * (__ldcs(x54 + c - 1) + __ldcs(x55 + c - 1));
                }
                __stcs(op + (HO - 1) * WO + c, v);
            }
        }

        // ---- interior rows r = 1..56: one warp per row, float2, batched loads ----
        const float wLr = leftz  ? 0.0f : leftW[ch];
        const float wRr = rightz ? 0.0f : rightW[ch];

        // Phase 1: issue all 7 loads (MLP = 7)
        float2 g[7];
        #pragma unroll
        for (int k = 0; k < 7; k++) {
            g[k] = make_float2(0.0f, 0.0f);
            if (ld) g[k] = __ldcs((const float2*)(xp + (warp + 8 * k) * Ww + 2 * lane));
        }

        // Phase 2: shuffle + select + store
        #pragma unroll
        for (int k = 0; k < 7; k++) {
            const int r = 1 + warp + 8 * k;
            const float upx = __shfl_up_sync(0xffffffffu, g[k].x, 1);
            const float upy = __shfl_up_sync(0xffffffffu, g[k].y, 1);
            if (st) {
                const float o_lo = (lane == 0)  ? wLr * (g[k].x + g[k].y) : upy;
                const float o_hi = (lane == 28) ? wRr * (upx + upy)       : g[k].x;
                __stcs((float2*)(op + r * WO + 2 * lane), make_float2(o_lo, o_hi));
            }
        }
    }
}

extern "C" void kernel_launch(void* const* d_in, const int* in_sizes, int n_in,
                              void* d_out, int out_size)
{
    const float* x         = (const float*)d_in[0];
    const float* topW      = (const float*)d_in[1];
    const float* botW      = (const float*)d_in[2];
    const float* leftW     = (const float*)d_in[3];
    const float* rightW    = (const float*)d_in[4];
    const float* topleftW  = (const float*)d_in[5];
    const float* toprightW = (const float*)d_in[6];
    const float* botleftW  = (const float*)d_in[7];
    const float* botrightW = (const float*)d_in[8];
    const int*   num_patches = (const int*)d_in[10];

    const int planes = in_sizes[0] / PLANE_IN;   // b * C = 16384

    int grid = 148 * 8;
    if (grid > planes) grid = planes;

    weight_pad2d_kernel<<<grid, 256>>>(
        x, topW, botW, leftW, rightW,
        topleftW, toprightW, botleftW, botrightW,
        num_patches, planes, (float*)d_out);
}